// round 1
// baseline (speedup 1.0000x reference)
#include <cuda_runtime.h>
#include <math.h>

#define DD 128
#define WIN 15
#define WW (2*WIN+1)
#define MAXB 4
#define MAXS 4096

// scratch (no allocations allowed)
__device__ float g_invnorm[MAXB*MAXS];
__device__ int   g_spk[MAXB*MAXS];
__device__ float g_band[(size_t)MAXB*MAXS*WW];
__device__ float g_dinv[MAXB*MAXS];

// Kernel 1: per-row inverse norm + speaker argmax
__global__ void prep_kernel(const float* __restrict__ x,
                            const float* __restrict__ qmask,
                            int B, int S, int NSPK) {
    int t = blockIdx.x * blockDim.x + threadIdx.x;
    if (t >= B * S) return;
    int b = t / S, s = t % S;
    const float4* xr = (const float4*)(x + (size_t)t * DD);
    float ss = 0.f;
#pragma unroll
    for (int k = 0; k < DD / 4; k++) {
        float4 v = xr[k];
        ss += v.x * v.x + v.y * v.y + v.z * v.z + v.w * v.w;
    }
    float norm = sqrtf(ss);
    g_invnorm[t] = 1.f / fmaxf(norm, 1e-8f);

    const float* q = qmask + ((size_t)s * B + b) * NSPK;
    float best = q[0];
    int bi = 0;
    for (int k = 1; k < NSPK; k++) {
        float v = q[k];
        if (v > best) { best = v; bi = k; }  // strict > keeps first max (JAX argmax)
    }
    g_spk[t] = bi;
}

// Kernel 2: one warp per (b,i): cnt -> band a_ij -> deg -> dinv
__global__ void band_kernel(const float* __restrict__ x,
                            const int* __restrict__ dia_len,
                            int B, int S) {
    int warp = (blockIdx.x * blockDim.x + threadIdx.x) >> 5;
    int lane = threadIdx.x & 31;
    if (warp >= B * S) return;
    int b = warp / S, i = warp % S;
    int len = dia_len[b];
    bool valid_i = (i < len);
    int base = b * S;

    float inv_i = g_invnorm[base + i];
    int spk_i = g_spk[base + i];
    float4 xi = ((const float4*)(x + (size_t)(base + i) * DD))[lane];
    xi.x *= inv_i; xi.y *= inv_i; xi.z *= inv_i; xi.w *= inv_i;

    int lo = max(i - WIN, 0), hi = min(i + WIN, S - 1);

    // count of same-speaker valid tokens in window (includes i itself)
    int cnt = 0;
    if (valid_i) {
        for (int j = lo; j <= hi; j++)
            if (j < len && g_spk[base + j] == spk_i) cnt++;
    }

    float deg = 0.f;
    float* bp = g_band + (size_t)(base + i) * WW;
    for (int jj = 0; jj < WW; jj++) {
        int j = i - WIN + jj;
        float a = 0.f;
        if (valid_i && j >= 0 && j < S && j < len) {
            float inv_j = g_invnorm[base + j];
            float4 xj = ((const float4*)(x + (size_t)(base + j) * DD))[lane];
            float dot = xi.x * xj.x + xi.y * xj.y + xi.z * xj.z + xi.w * xj.w;
            dot *= inv_j;
#pragma unroll
            for (int off = 16; off; off >>= 1)
                dot += __shfl_xor_sync(0xffffffffu, dot, off);
            float c = fminf(fmaxf(dot, -1.f), 1.f);
            float w = 1.f - acosf(c) * 0.31830988618379067f;  // 1 - acos/pi
            bool same = (g_spk[base + j] == spk_i);
            a = w * ((cnt > 1 && same) ? 2.f : 1.f);
            deg += a;
        }
        // all lanes hold identical a; distribute the band stores across lanes
        if (lane == (jj & 31)) bp[jj] = a;
    }
    if (lane == 0)
        g_dinv[base + i] = (deg > 0.f) ? rsqrtf(deg) : 1.f;
}

// Kernel 3: scatter normalized band values into the zeroed dense output
__global__ void scatter_kernel(float* __restrict__ out, int B, int S) {
    int t = blockIdx.x * blockDim.x + threadIdx.x;
    int total = B * S * WW;
    if (t >= total) return;
    int jj = t % WW;
    int rest = t / WW;
    int i = rest % S;
    int b = rest / S;
    int j = i - WIN + jj;
    if (j < 0 || j >= S) return;
    float a = g_band[(size_t)t];
    float v = a * g_dinv[b * S + i] * g_dinv[b * S + j];
    out[((size_t)b * S + i) * S + j] = v;
}

extern "C" void kernel_launch(void* const* d_in, const int* in_sizes, int n_in,
                              void* d_out, int out_size) {
    const float* x       = (const float*)d_in[0];
    const float* qmask   = (const float*)d_in[1];
    const int*   dia_len = (const int*)d_in[2];
    float* out = (float*)d_out;

    int B = in_sizes[2];
    int S = in_sizes[0] / (B * DD);
    int NSPK = in_sizes[1] / (B * S);

    // zero the dense output (band entries overwritten below)
    cudaMemsetAsync(out, 0, (size_t)out_size * sizeof(float), 0);

    int n = B * S;
    prep_kernel<<<(n + 255) / 256, 256>>>(x, qmask, B, S, NSPK);
    band_kernel<<<(n * 32 + 127) / 128, 128>>>(x, dia_len, B, S);

    int m = n * WW;
    scatter_kernel<<<(m + 255) / 256, 256>>>(out, B, S);
}

// round 2
// speedup vs baseline: 1.2425x; 1.2425x over previous
#include <cuda_runtime.h>
#include <math.h>

#define DD 128
#define WIN 15
#define WW (2*WIN+1)
#define MAXB 4
#define MAXS 4096
#define RPB 8                 // band rows per block
#define TROWS (RPB + 2*WIN)   // 38 smem rows

__device__ float g_invnorm[MAXB*MAXS];
__device__ int   g_spk[MAXB*MAXS];
__device__ float g_band[(size_t)MAXB*MAXS*WW];
__device__ float g_dinv[MAXB*MAXS];

// ---------------- Kernel 1: inv-norms (8 threads/row) + speaker argmax ----------------
__global__ __launch_bounds__(256)
void prep_kernel(const float* __restrict__ x,
                 const float* __restrict__ qmask,
                 int B, int S, int NSPK) {
    int t = blockIdx.x * blockDim.x + threadIdx.x;
    int row = t >> 3;          // 8 threads per row
    int sub = t & 7;
    if (row >= B * S) return;

    const float4* xr = (const float4*)(x + (size_t)row * DD);
    float ss = 0.f;
#pragma unroll
    for (int k = 0; k < 4; k++) {
        float4 v = xr[sub * 4 + k];
        ss += v.x * v.x + v.y * v.y + v.z * v.z + v.w * v.w;
    }
    // reduce within the 8-lane group (lanes share t/8)
#pragma unroll
    for (int off = 4; off; off >>= 1)
        ss += __shfl_xor_sync(0xffffffffu, ss, off);

    if (sub == 0)
        g_invnorm[row] = 1.f / fmaxf(sqrtf(ss), 1e-8f);

    if (sub == 1) {
        int b = row / S, s = row % S;
        const float* q = qmask + ((size_t)s * B + b) * NSPK;
        float best = q[0];
        int bi = 0;
        for (int k = 1; k < NSPK; k++) {
            float v = q[k];
            if (v > best) { best = v; bi = k; }   // strict > = JAX first-max
        }
        g_spk[row] = bi;
    }
}

// ---------------- Kernel 2: band values + dinv, smem-tiled ----------------
__global__ __launch_bounds__(256)
void band_kernel(const float* __restrict__ x,
                 const int* __restrict__ dia_len,
                 int B, int S) {
    __shared__ float sx[TROWS * DD];
    __shared__ int   sspk[TROWS];

    int b  = blockIdx.y;
    int i0 = blockIdx.x * RPB;
    int base = b * S;
    int len = dia_len[b];
    int gr0 = i0 - WIN;

    // cooperative load of normalized rows [gr0, gr0+TROWS)
    float4* sx4 = (float4*)sx;
    const float4* x4 = (const float4*)(x + (size_t)base * DD);
    for (int idx = threadIdx.x; idx < TROWS * (DD/4); idx += blockDim.x) {
        int r = idx >> 5;            // smem row
        int q = idx & 31;            // float4 within row
        int gr = gr0 + r;
        float4 v = {0.f, 0.f, 0.f, 0.f};
        if (gr >= 0 && gr < S) {
            v = x4[(size_t)gr * 32 + q];
            float inv = g_invnorm[base + gr];
            v.x *= inv; v.y *= inv; v.z *= inv; v.w *= inv;
        }
        sx4[idx] = v;
    }
    if (threadIdx.x < TROWS) {
        int gr = gr0 + threadIdx.x;
        sspk[threadIdx.x] = (gr >= 0 && gr < S) ? g_spk[base + gr] : -1;
    }
    __syncthreads();

    int w = threadIdx.x >> 5;        // warp = local row
    int lane = threadIdx.x & 31;
    int i = i0 + w;
    if (i >= S) return;
    int li = WIN + w;                // smem row of i
    bool valid_i = (i < len);
    int spk_i = sspk[li];

    float4 xi = ((float4*)(sx + li * DD))[lane];

    // same-speaker count inside window (all lanes redundantly)
    int cnt = 0;
    if (valid_i) {
#pragma unroll
        for (int jj = 0; jj < WW; jj++) {
            int j = i - WIN + jj;
            if (j >= 0 && j < len && sspk[w + jj] == spk_i) cnt++;
        }
    }

    float deg = 0.f;
    float* bp = g_band + (size_t)(base + i) * WW;
#pragma unroll
    for (int jj = 0; jj < WW; jj++) {
        int j = i - WIN + jj;
        float a = 0.f;
        if (valid_i && j >= 0 && j < len) {
            float4 xj = ((float4*)(sx + (w + jj) * DD))[lane];
            float dot = xi.x * xj.x + xi.y * xj.y + xi.z * xj.z + xi.w * xj.w;
#pragma unroll
            for (int off = 16; off; off >>= 1)
                dot += __shfl_xor_sync(0xffffffffu, dot, off);
            float c = fminf(fmaxf(dot, -1.f), 1.f);
            float wgt = 1.f - acosf(c) * 0.31830988618379067f;
            bool same = (sspk[w + jj] == spk_i);
            a = wgt * ((cnt > 1 && same) ? 2.f : 1.f);
            deg += a;
        }
        if (lane == jj) bp[jj] = a;   // lanes 0..30 write consecutive floats
    }
    if (lane == 0)
        g_dinv[base + i] = (deg > 0.f) ? rsqrtf(deg) : 1.f;
}

// ---------------- Kernel 3: fused zero-fill + normalized band write ----------------
__global__ __launch_bounds__(256)
void fill_kernel(float* __restrict__ out, int B, int S) {
    int row = blockIdx.x;            // b*S + i
    int b = row / S, i = row % S;
    float di = g_dinv[row];
    const float* bp = g_band + (size_t)row * WW;
    float4* orow = (float4*)(out + (size_t)row * S);
    int lo = i - WIN;

    for (int c4 = threadIdx.x; c4 * 4 < S; c4 += blockDim.x) {
        int j0 = c4 * 4;
        float4 v = {0.f, 0.f, 0.f, 0.f};
        int d0 = j0 - lo;
        if (d0 > -4 && d0 < WW) {     // this float4 overlaps the band
            float* ve = &v.x;
#pragma unroll
            for (int e = 0; e < 4; e++) {
                int d = d0 + e, j = j0 + e;
                if (d >= 0 && d < WW && j < S)
                    ve[e] = bp[d] * di * g_dinv[b * S + j];
            }
        }
        __stcs(&orow[c4], v);
    }
}

extern "C" void kernel_launch(void* const* d_in, const int* in_sizes, int n_in,
                              void* d_out, int out_size) {
    const float* x       = (const float*)d_in[0];
    const float* qmask   = (const float*)d_in[1];
    const int*   dia_len = (const int*)d_in[2];
    float* out = (float*)d_out;

    int B = in_sizes[2];
    int S = in_sizes[0] / (B * DD);
    int NSPK = in_sizes[1] / (B * S);
    int n = B * S;

    prep_kernel<<<(n * 8 + 255) / 256, 256>>>(x, qmask, B, S, NSPK);

    dim3 bgrid((S + RPB - 1) / RPB, B);
    band_kernel<<<bgrid, 256>>>(x, dia_len, B, S);

    fill_kernel<<<n, 256>>>(out, B, S);
}